// round 1
// baseline (speedup 1.0000x reference)
#include <cuda_runtime.h>
#include <math.h>

// Problem constants
#define B_    16
#define CIN   48
#define COUT  48
#define HH    128
#define WW    128
#define SP    7
#define TAPS  49          // SP*SP
#define KDIM  98          // 2*TAPS (cos block + sin block)

// Conv tiling
#define TH    8           // output rows per block
#define TW    32          // output cols per block
#define XS_H  (TH + 6)    // 14
#define XS_W  (TW + 6)    // 38
#define XS_PW 40          // padded row (bank spread, float4-aligned rows: 160B)

// Scratch for per-batch rotated filters: F[b][m][tap][n]
__device__ float g_F[(size_t)B_ * CIN * TAPS * COUT];

// ---------------------------------------------------------------------------
// Kernel A: basis + filter generation.
// One block per (b, tap). bs[k] = basis[b, tap_i, tap_j, k]; then
// F[b][m][tap][n] = sum_k bs[k] * W[n][k][m].
// ---------------------------------------------------------------------------
__global__ void gen_filters_kernel(const float* __restrict__ theta,
                                   const float* __restrict__ W)
{
    const int blk = blockIdx.x;      // b*TAPS + tap
    const int b   = blk / TAPS;
    const int tap = blk % TAPS;
    const int i   = tap / SP;        // kernel row
    const int j   = tap % SP;        // kernel col

    __shared__ float bs[KDIM];

    const int t = threadIdx.x;
    if (t < KDIM) {
        const float th = theta[b];
        const float ct = cosf(th), st = sinf(th);
        // meshgrid(x, x) 'xy': inX[i][j] = x[j], inY[i][j] = x[i], x = (idx-3)/3
        const float xj = (float)(j - 3) * (1.0f / 3.0f);
        const float xi = (float)(i - 3) * (1.0f / 3.0f);
        const float Xr = ct * xj - st * xi;
        const float Yr = st * xj + ct * xi;
        const float r2 = Xr * Xr + Yr * Yr;
        const float mask = expf(-fmaxf(r2 - 1.0f, 0.0f) * 5.0f);  // /0.2

        const int  q    = t;
        const bool cosp = (q < TAPS);
        const int  qq   = cosp ? q : q - TAPS;
        const int  k    = qq / SP;
        const int  l    = qq % SP;
        const float kk = (k > 3) ? (float)(k - SP) : (float)k;
        const float ll = (l > 3) ? (float)(l - SP) : (float)l;
        const float v  = 2.6927937030769655f;   // pi/7 * 6
        const float ang = kk * v * Xr + ll * v * Yr;
        bs[t] = (cosp ? cosf(ang) : sinf(ang)) * mask;
    }
    __syncthreads();

    // 2304 outputs (n,m) per block, 256 threads -> 9 each.
    for (int o = t; o < COUT * CIN; o += blockDim.x) {
        const int n = o / CIN;
        const int m = o % CIN;
        const float* wp = W + (size_t)n * KDIM * CIN + m;   // W[n][k][m], stride CIN over k
        float s = 0.0f;
        #pragma unroll 7
        for (int k = 0; k < KDIM; ++k)
            s += bs[k] * wp[(size_t)k * CIN];
        g_F[(((size_t)b * CIN + m) * TAPS + tap) * COUT + n] = s;
    }
}

// ---------------------------------------------------------------------------
// Kernel B: grouped direct conv.
// Block = (b, 8x32 output tile), 256 threads covering all 48 output channels:
//   thread = (cg in 0..3 -> 12 channels) x (64 pixel-slots -> 8 rows x 8 col-quads)
// Loop over input channel m: stage x tile (14x38) + filters F[b][m] (49x48)
// in smem, then 49 taps x 12 ch x 4 px register-blocked FFMAs.
// Per thread: 48*49*48 = 112,896 FFMAs; ~14 FFMAs per LDS.
// ---------------------------------------------------------------------------
__global__ __launch_bounds__(256, 2)
void rot_conv_kernel(const float* __restrict__ x,
                     const float* __restrict__ cbias,
                     float* __restrict__ y)
{
    __shared__ float xs[XS_H][XS_PW];
    __shared__ float fs[TAPS * COUT];   // [tap][n], n contiguous

    const int b   = blockIdx.z;
    const int by  = blockIdx.y;         // 0..15
    const int bx  = blockIdx.x;         // 0..3
    const int tid = threadIdx.x;

    const int pix  = tid & 63;
    const int cg   = tid >> 6;          // 0..3
    const int row  = pix >> 3;          // 0..7
    const int col0 = (pix & 7) << 2;    // 0,4,...,28
    const int n0   = cg * 12;

    float acc[12][4];
    #pragma unroll
    for (int a = 0; a < 12; ++a)
        #pragma unroll
        for (int p = 0; p < 4; ++p)
            acc[a][p] = 0.0f;

    const float* xb = x   + (size_t)b * CIN * HH * WW;
    const float* Fb = g_F + (size_t)b * CIN * TAPS * COUT;

    const int gr0 = by * TH - 3;
    const int gc0 = bx * TW - 3;

    for (int m = 0; m < CIN; ++m) {
        // --- stage x tile (with zero halo) ---
        const float* xm = xb + (size_t)m * HH * WW;
        for (int idx = tid; idx < XS_H * XS_W; idx += 256) {
            const int r  = idx / XS_W;
            const int c2 = idx % XS_W;
            const int gr = gr0 + r;
            const int gc = gc0 + c2;
            float v = 0.0f;
            if (gr >= 0 && gr < HH && gc >= 0 && gc < WW)
                v = xm[gr * WW + gc];
            xs[r][c2] = v;
        }
        // --- stage filters for this (b, m): 2352 floats = 588 float4 ---
        {
            const float4* Fm  = (const float4*)(Fb + (size_t)m * TAPS * COUT);
            float4*       fsv = (float4*)fs;
            for (int idx = tid; idx < (TAPS * COUT) / 4; idx += 256)
                fsv[idx] = Fm[idx];
        }
        __syncthreads();

        #pragma unroll 1
        for (int i = 0; i < SP; ++i) {
            // sliding window of 10 x-values covering j=0..6, p=0..3
            float xw[10];
            #pragma unroll
            for (int c2 = 0; c2 < 10; ++c2)
                xw[c2] = xs[row + i][col0 + c2];

            #pragma unroll
            for (int j = 0; j < SP; ++j) {
                const float* wp = fs + (i * SP + j) * COUT + n0;
                #pragma unroll
                for (int nn = 0; nn < 12; ++nn) {
                    const float w = wp[nn];
                    acc[nn][0] = fmaf(w, xw[j + 0], acc[nn][0]);
                    acc[nn][1] = fmaf(w, xw[j + 1], acc[nn][1]);
                    acc[nn][2] = fmaf(w, xw[j + 2], acc[nn][2]);
                    acc[nn][3] = fmaf(w, xw[j + 3], acc[nn][3]);
                }
            }
        }
        __syncthreads();
    }

    // --- epilogue: + c, vectorized store ---
    const int gr = by * TH + row;
    const int gc = bx * TW + col0;
    #pragma unroll
    for (int nn = 0; nn < 12; ++nn) {
        const int n = n0 + nn;
        const float cb = cbias[n];
        float4 o;
        o.x = acc[nn][0] + cb;
        o.y = acc[nn][1] + cb;
        o.z = acc[nn][2] + cb;
        o.w = acc[nn][3] + cb;
        *(float4*)(y + ((((size_t)b * COUT + n) * HH + gr) * WW + gc)) = o;
    }
}

// ---------------------------------------------------------------------------
// kernel_launch: inputs per metadata order: x, theta, weights, c
// ---------------------------------------------------------------------------
extern "C" void kernel_launch(void* const* d_in, const int* in_sizes, int n_in,
                              void* d_out, int out_size)
{
    const float* x      = (const float*)d_in[0];  // (16,48,128,128)
    const float* theta  = (const float*)d_in[1];  // (16,1)
    const float* wts    = (const float*)d_in[2];  // (48,98,48)
    const float* cbias  = (const float*)d_in[3];  // (1,48,1,1)
    float*       y      = (float*)d_out;          // (16,48,128,128)

    (void)in_sizes; (void)n_in; (void)out_size;

    gen_filters_kernel<<<B_ * TAPS, 256>>>(theta, wts);

    dim3 grid(WW / TW, HH / TH, B_);   // (4, 16, 16)
    rot_conv_kernel<<<grid, 256>>>(x, cbias, y);
}

// round 3
// speedup vs baseline: 2.6462x; 2.6462x over previous
#include <cuda_runtime.h>
#include <cstdint>
#include <math.h>

// ---------------- problem constants ----------------
#define B_    16
#define CIN   48
#define COUT  48
#define HH    128
#define WW    128
#define SP    7
#define TAPS  49
#define KDIM  98

// ---------------- tiling ----------------
#define CM     8                 // channels per K-chunk (K=8 per mma)
#define NCH    (CIN/CM)          // 6
#define RG     4                 // output rows per CTA
#define SLAB_RR 10               // RG + 6 halo
#define SLAB_CC 140              // 134 needed, padded
#define SLAB_FLOATS (SLAB_RR*SLAB_CC*CM)   // 11200
#define FILT_FLOATS (TAPS*COUT*CM)         // 18816
#define BIAS_OFF    (SLAB_FLOATS + FILT_FLOATS)          // 30016
#define SMEM_FLOATS (BIAS_OFF + 64)                      // 30080
#define SMEM_BYTES  (SMEM_FLOATS * 4)                    // 120320

// filter scratch (permuted channel-minor, tf32-rounded): F[b][ch][tap][n][p8]
__device__ float g_F[(size_t)B_ * NCH * TAPS * COUT * CM];

// ---------------- helpers ----------------
__device__ __forceinline__ float tf32r(float f) {
    uint32_t u;
    asm("cvt.rna.tf32.f32 %0, %1;" : "=r"(u) : "f"(f));
    return __uint_as_float(u);
}

__device__ __forceinline__ void mma_tf32(float* c,
                                         uint32_t a0, uint32_t a1, uint32_t a2, uint32_t a3,
                                         uint32_t b0, uint32_t b1) {
    asm volatile(
        "mma.sync.aligned.m16n8k8.row.col.f32.tf32.tf32.f32 "
        "{%0,%1,%2,%3},{%4,%5,%6,%7},{%8,%9},{%0,%1,%2,%3};"
        : "+f"(c[0]), "+f"(c[1]), "+f"(c[2]), "+f"(c[3])
        : "r"(a0), "r"(a1), "r"(a2), "r"(a3), "r"(b0), "r"(b1));
}

// ---------------------------------------------------------------------------
// Kernel A: filter generation.
// F[b][ch][tap][n][p] = tf32( sum_k basis[b,tap,k] * W[n][k][m] ),
// p = 2*(mm&3) + (mm>>2)  (k / k+4 pairs adjacent for LDS.64 fragments)
// ---------------------------------------------------------------------------
__global__ void gen_filters_kernel(const float* __restrict__ theta,
                                   const float* __restrict__ W)
{
    const int blk = blockIdx.x;
    const int b   = blk / TAPS;
    const int tap = blk % TAPS;
    const int i   = tap / SP;
    const int j   = tap % SP;

    __shared__ float bs[KDIM];

    const int t = threadIdx.x;
    if (t < KDIM) {
        const float th = theta[b];
        const float ct = cosf(th), st = sinf(th);
        const float xj = (float)(j - 3) * (1.0f / 3.0f);
        const float xi = (float)(i - 3) * (1.0f / 3.0f);
        const float Xr = ct * xj - st * xi;
        const float Yr = st * xj + ct * xi;
        const float r2 = Xr * Xr + Yr * Yr;
        const float mask = expf(-fmaxf(r2 - 1.0f, 0.0f) * 5.0f);

        const bool cosp = (t < TAPS);
        const int  qq   = cosp ? t : t - TAPS;
        const int  k    = qq / SP;
        const int  l    = qq % SP;
        const float kk = (k > 3) ? (float)(k - SP) : (float)k;
        const float ll = (l > 3) ? (float)(l - SP) : (float)l;
        const float v  = 2.6927937030769655f;   // pi/7 * 6
        const float ang = kk * v * Xr + ll * v * Yr;
        bs[t] = (cosp ? cosf(ang) : sinf(ang)) * mask;
    }
    __syncthreads();

    for (int o = t; o < COUT * CIN; o += blockDim.x) {
        const int n = o / CIN;
        const int m = o % CIN;
        const float* wp = W + (size_t)n * KDIM * CIN + m;
        float s = 0.0f;
        #pragma unroll 7
        for (int k = 0; k < KDIM; ++k)
            s += bs[k] * wp[(size_t)k * CIN];
        const int ch = m >> 3, mm = m & 7;
        const int p  = 2 * (mm & 3) + (mm >> 2);
        g_F[((((size_t)b * NCH + ch) * TAPS + tap) * COUT + n) * CM + p] = tf32r(s);
    }
}

// ---------------------------------------------------------------------------
// Kernel B: tf32 mma.sync implicit-GEMM grouped conv.
// CTA = (b, 4 output rows). 8 warps: warp w -> row (w>>1), cols 64*(w&1)..+63.
// Warp tile: M=64 px x N=48 outs = acc[4][6][4]. K loop = 6 chunks x 49 taps.
// ---------------------------------------------------------------------------
__global__ __launch_bounds__(256, 1)
void conv_mma_kernel(const float* __restrict__ x,
                     const float* __restrict__ cbias,
                     float* __restrict__ y)
{
    extern __shared__ float sm[];
    float* slab = sm;                 // [10][140][8] permuted channels
    float* filt = sm + SLAB_FLOATS;   // [49][48][8] permuted channels
    float* bias = sm + BIAS_OFF;

    const int tid  = threadIdx.x;
    const int wid  = tid >> 5;
    const int lane = tid & 31;
    const int b    = blockIdx.x >> 5;
    const int rg   = blockIdx.x & 31;
    const int h0   = rg * RG;

    const int g  = lane >> 2;         // group id 0..7
    const int t4 = lane & 3;          // thread-in-group
    const int rw   = wid >> 1;        // warp row 0..3
    const int col0 = (wid & 1) * 64;  // warp col base

    if (tid < COUT) bias[tid] = cbias[tid];

    float acc[4][6][4];
    #pragma unroll
    for (int mt = 0; mt < 4; ++mt)
        #pragma unroll
        for (int nt = 0; nt < 6; ++nt)
            #pragma unroll
            for (int q = 0; q < 4; ++q)
                acc[mt][nt][q] = 0.0f;

    const float* xb = x + (size_t)b * CIN * HH * WW;

    #pragma unroll 1
    for (int ch = 0; ch < NCH; ++ch) {
        __syncthreads();
        // zero slab (halo stays zero)
        for (int q = tid; q < SLAB_FLOATS / 4; q += 256)
            ((float4*)slab)[q] = make_float4(0.f, 0.f, 0.f, 0.f);
        __syncthreads();

        // fill slab interior: S[rr][3+gc][perm(mm)] = tf32(x[b][8ch+mm][h0-3+rr][gc])
        const float* xc = xb + (size_t)ch * CM * HH * WW;
        for (int q = tid; q < CM * SLAB_RR * 32; q += 256) {
            const int quad = q & 31;
            const int r2   = q >> 5;            // 0..79
            const int mm   = r2 / SLAB_RR;
            const int rr   = r2 - mm * SLAB_RR;
            const int gr   = h0 - 3 + rr;
            if (gr >= 0 && gr < HH) {
                const float4 v = *(const float4*)(xc + ((size_t)mm * HH + gr) * WW + 4 * quad);
                const int p = 2 * (mm & 3) + (mm >> 2);
                float* d = slab + (rr * SLAB_CC + 3 + 4 * quad) * CM + p;
                d[0]      = tf32r(v.x);
                d[CM]     = tf32r(v.y);
                d[2 * CM] = tf32r(v.z);
                d[3 * CM] = tf32r(v.w);
            }
        }
        // stage filters for this chunk (already permuted + tf32-rounded)
        {
            const float4* Fs = (const float4*)(g_F + (size_t)(b * NCH + ch) * TAPS * COUT * CM);
            float4* fd = (float4*)filt;
            for (int q = tid; q < FILT_FLOATS / 4; q += 256)
                fd[q] = Fs[q];
        }
        __syncthreads();

        #pragma unroll 1
        for (int i = 0; i < SP; ++i) {
            const int abase = (rw + i) * (SLAB_CC * CM);
            #pragma unroll
            for (int j = 0; j < SP; ++j) {
                const int tap = i * SP + j;
                // B fragments: filt[tap][n = nt*8+g][2*t4 .. +1]
                uint2 Bf[6];
                #pragma unroll
                for (int nt = 0; nt < 6; ++nt)
                    Bf[nt] = *(const uint2*)&filt[(tap * COUT + nt * 8 + g) * CM + 2 * t4];
                #pragma unroll
                for (int mt = 0; mt < 4; ++mt) {
                    const int ai = abase + (col0 + mt * 16 + g + j) * CM + 2 * t4;
                    const uint2 a02 = *(const uint2*)&slab[ai];           // px = g
                    const uint2 a13 = *(const uint2*)&slab[ai + 8 * CM];  // px = g+8
                    #pragma unroll
                    for (int nt = 0; nt < 6; ++nt)
                        mma_tf32(acc[mt][nt], a02.x, a13.x, a02.y, a13.y,
                                 Bf[nt].x, Bf[nt].y);
                }
            }
        }
    }

    // epilogue
    const int row = h0 + rw;
    #pragma unroll
    for (int nt = 0; nt < 6; ++nt) {
        const int n  = nt * 8 + 2 * t4;
        const float b0 = bias[n];
        const float b1 = bias[n + 1];
        float* y0 = y + (((size_t)b * COUT + n) * HH + row) * WW;
        float* y1 = y0 + (size_t)HH * WW;
        #pragma unroll
        for (int mt = 0; mt < 4; ++mt) {
            const int px = col0 + mt * 16 + g;
            y0[px]     = acc[mt][nt][0] + b0;
            y1[px]     = acc[mt][nt][1] + b1;
            y0[px + 8] = acc[mt][nt][2] + b0;
            y1[px + 8] = acc[mt][nt][3] + b1;
        }
    }
}

// ---------------------------------------------------------------------------
extern "C" void kernel_launch(void* const* d_in, const int* in_sizes, int n_in,
                              void* d_out, int out_size)
{
    const float* x     = (const float*)d_in[0];  // (16,48,128,128)
    const float* theta = (const float*)d_in[1];  // (16,1)
    const float* wts   = (const float*)d_in[2];  // (48,98,48)
    const float* cbias = (const float*)d_in[3];  // (1,48,1,1)
    float*       y     = (float*)d_out;          // (16,48,128,128)

    (void)in_sizes; (void)n_in; (void)out_size;

    static int smem_set = 0;
    if (!smem_set) {
        cudaFuncSetAttribute(conv_mma_kernel,
                             cudaFuncAttributeMaxDynamicSharedMemorySize, SMEM_BYTES);
        smem_set = 1;
    }

    gen_filters_kernel<<<B_ * TAPS, 256>>>(theta, wts);
    conv_mma_kernel<<<B_ * 32, 256, SMEM_BYTES>>>(x, cbias, y);
}